// round 4
// baseline (speedup 1.0000x reference)
#include <cuda_runtime.h>
#include <cuda_bf16.h>
#include <cstdint>

// image_output: [8, 512, 512, 32] f32; slic: [8,512,512,1] i32 in [0,256]
// out[s][b][c] = sum(img where slic-1==s) / count(nonzero img where slic-1==s)

#define BATCH 8
#define HW (512 * 512)
#define CH 32
#define NSEG 256
#define DROW NSEG                 // dummy row for slic==0 pixels
#define ROWS (NSEG + 1)

#define WPB 2
#define BPB 55                    // 440 blocks = one wave at 3 blocks/SM
#define GRID_ACC (BATCH * BPB)
#define CHUNK ((HW + BPB - 1) / BPB)       // 4767

#define ACCF (ROWS * CH)                    // 8224 floats (sum rows, dummy last)
#define WARP_WORDS (ACCF + ROWS + 3)        // + count ints, padded to 16B
#define SMEM_BYTES (WPB * WARP_WORDS * 4)   // 67872 per block -> 3 blocks/SM

#define PARTF (NSEG * CH + NSEG)            // per-block partial: sums + counts

__device__ float g_part[GRID_ACC][PARTF];
__device__ float g_zc[BATCH][NSEG][CH];     // exact-zero corrections.
// INVARIANT: g_zc == 0 at every kernel_launch entry (statics are
// zero-initialized; finalize re-zeros after consuming).

// ---------------------------------------------------------------------------
// Per-round processing: 16 pixels, values v[16], lane<16 holds pixel's slic.
// ---------------------------------------------------------------------------
__device__ __forceinline__ void process16(
    float v[16], int mysv, float* __restrict__ acc, int* __restrict__ cnt,
    int batch, int lane)
{
    const unsigned FULL = 0xffffffffu;
    int myrow = (mysv == 0) ? DROW : (mysv - 1);

    // Collision detection among the 16 pixel rows (warp-uniform outcome).
    int d1 = __shfl_up_sync(FULL, mysv, 1);
    int d2 = __shfl_up_sync(FULL, mysv, 2);
    bool bad = (lane < 16) && (((lane >= 1) && (mysv == d1)) ||
                               ((lane >= 2) && (mysv == d2)));
    unsigned badm = __ballot_sync(FULL, bad);

    // Segment pixel counts: dedup equal rows among lanes 0..15, leader adds.
    if (lane < 16) {
        unsigned m = __match_any_sync(0x0000ffffu, myrow);
        if (lane == (__ffs(m) - 1)) cnt[myrow] += __popc(m);
    }

    int row[16];
    #pragma unroll
    for (int u = 0; u < 16; ++u) row[u] = __shfl_sync(FULL, myrow, u);

    bool zany = false;
    #pragma unroll
    for (int u = 0; u < 16; ++u) zany |= (v[u] == 0.0f);

    if (badm == 0) {
        // FAST path (~89% of rounds): no duplicates within distance 2 ->
        // repair-free pipelined RMW, no serial cross-iteration dependency.
        float p0 = acc[row[0] * CH + lane];
        float p1 = acc[row[1] * CH + lane];
        #pragma unroll
        for (int u = 0; u < 16; ++u) {
            float a = p0 + v[u];
            float np = 0.0f;
            if (u + 2 < 16) np = acc[row[u + 2] * CH + lane]; // prefetch first
            acc[row[u] * CH + lane] = a;
            p0 = p1; p1 = np;
        }
    } else {
        // SLOW path: exact depth-2 repair (handles any duplicate pattern).
        float p0 = acc[row[0] * CH + lane];
        float p1 = acc[row[1] * CH + lane];
        int   lr = -1, l2r = -1;
        float lv = 0.f, l2v = 0.f;
        #pragma unroll
        for (int u = 0; u < 16; ++u) {
            float a = p0;
            a = (row[u] == l2r) ? l2v : a;
            a = (row[u] == lr)  ? lv  : a;
            a += v[u];
            float np = 0.0f;
            if (u + 2 < 16) np = acc[row[u + 2] * CH + lane];
            acc[row[u] * CH + lane] = a;
            l2r = lr;  l2v = lv;
            lr = row[u]; lv = a;
            p0 = p1; p1 = np;
        }
    }

    // Rare: exact-zero image entries (warp-uniformly not taken).
    if (__ballot_sync(FULL, zany)) {
        #pragma unroll
        for (int u = 0; u < 16; ++u)
            if (v[u] == 0.0f && row[u] != DROW)
                atomicAdd(&g_zc[batch][row[u]][lane], 1.0f);
    }
}

// ---------------------------------------------------------------------------
// Kernel 1: fused segmented accumulation + counting.
// Double-buffered rounds of 16 px/warp; warp-private smem accumulators.
// ---------------------------------------------------------------------------
__global__ void __launch_bounds__(WPB * 32, 3)
accum_kernel(const float* __restrict__ img, const int* __restrict__ slic) {
    extern __shared__ float smem[];
    const int warp = threadIdx.x >> 5;
    const int lane = threadIdx.x & 31;
    float* acc = smem + warp * WARP_WORDS;
    int*   cnt = (int*)(acc + ACCF);

    float4* a4 = (float4*)acc;
    for (int i = lane; i < ACCF / 4; i += 32)
        a4[i] = make_float4(0.f, 0.f, 0.f, 0.f);
    for (int i = lane; i < ROWS; i += 32) cnt[i] = 0;
    __syncwarp();

    const int batch = blockIdx.x / BPB;
    const int blk   = blockIdx.x % BPB;
    const float* imgb  = img  + (size_t)batch * HW * CH;
    const int*   slicb = slic + (size_t)batch * HW;

    const int start = blk * CHUNK;
    int end = start + CHUNK; if (end > HW) end = HW;
    const int n = end - start;
    const int nfull = n >> 5;                  // 32-px block rounds

    const float* ib = imgb + (size_t)(start + warp * 16) * CH + lane;
    const int*   sp = slicb + start + warp * 16;

    float v[16]; int mysv = 0;
    if (nfull > 0) {
        #pragma unroll
        for (int u = 0; u < 16; ++u) v[u] = __ldcs(ib + u * CH);
        mysv = sp[lane & 15];
    }

    for (int r = 0; r < nfull - 1; ++r) {
        // Issue NEXT round's loads before processing this round (hide DRAM).
        const float* ibn = ib + 32 * CH;
        float vn[16];
        #pragma unroll
        for (int u = 0; u < 16; ++u) vn[u] = __ldcs(ibn + u * CH);
        int svn = (sp + 32)[lane & 15];

        process16(v, mysv, acc, cnt, batch, lane);

        #pragma unroll
        for (int u = 0; u < 16; ++u) v[u] = vn[u];
        mysv = svn; ib = ibn; sp += 32;
    }
    if (nfull > 0)
        process16(v, mysv, acc, cnt, batch, lane);

    // Tail: < 32 pixels.
    for (int p = start + (nfull << 5) + warp; p < end; p += WPB) {
        int s = slicb[p];
        int rw = (s == 0) ? DROW : (s - 1);
        float x = imgb[(size_t)p * CH + lane];
        acc[rw * CH + lane] += x;
        if (lane == 0) cnt[rw] += 1;
        if (x == 0.0f && rw != DROW)
            atomicAdd(&g_zc[batch][rw][lane], 1.0f);
    }

    // Merge the two warps; stream partial (256 sum rows + 256 counts).
    __syncthreads();
    const float4* p0w = (const float4*)(smem);
    const float4* p1w = (const float4*)(smem + WARP_WORDS);
    float4* outp = (float4*)g_part[blockIdx.x];
    #pragma unroll 4
    for (int i = threadIdx.x; i < NSEG * CH / 4; i += WPB * 32) {
        float4 a = p0w[i], b = p1w[i];
        a.x += b.x; a.y += b.y; a.z += b.z; a.w += b.w;
        outp[i] = a;
    }
    const int* c0 = (const int*)(smem + ACCF);
    const int* c1 = (const int*)(smem + WARP_WORDS + ACCF);
    for (int i = threadIdx.x; i < NSEG; i += WPB * 32)
        g_part[blockIdx.x][NSEG * CH + i] = (float)(c0[i] + c1[i]);
}

// ---------------------------------------------------------------------------
// Kernel 2: reduce partials, divide, and restore the g_zc==0 invariant.
// ---------------------------------------------------------------------------
__global__ void finalize_kernel(float* __restrict__ out) {
    int idx = blockIdx.x * blockDim.x + threadIdx.x;   // 65536 = B*S*C
    int c = idx & (CH - 1);
    int s = (idx >> 5) & (NSEG - 1);
    int b = idx >> 13;

    float sum = 0.0f, cn = 0.0f;
    int pb = b * BPB;
    #pragma unroll 11
    for (int k = 0; k < BPB; ++k) {
        sum += g_part[pb + k][s * CH + c];             // coalesced over c
        cn  += g_part[pb + k][NSEG * CH + s];          // warp-broadcast
    }
    cn -= g_zc[b][s][c];
    g_zc[b][s][c] = 0.0f;                              // restore invariant
    out[((size_t)s * BATCH + b) * CH + c] = sum / cn;
}

// ---------------------------------------------------------------------------
extern "C" void kernel_launch(void* const* d_in, const int* in_sizes, int n_in,
                              void* d_out, int out_size) {
    const float* img  = (const float*)d_in[0];
    const int*   slic = (const int*)d_in[1];
    float* out = (float*)d_out;

    cudaFuncSetAttribute(accum_kernel,
                         cudaFuncAttributeMaxDynamicSharedMemorySize, SMEM_BYTES);
    accum_kernel<<<GRID_ACC, WPB * 32, SMEM_BYTES>>>(img, slic);

    finalize_kernel<<<256, 256>>>(out);
}

// round 5
// speedup vs baseline: 1.5051x; 1.5051x over previous
#include <cuda_runtime.h>
#include <cuda_bf16.h>
#include <cstdint>

// image_output: [8, 512, 512, 32] f32; slic: [8,512,512,1] i32 in [0,256]
// out[s][b][c] = sum(img where slic-1==s) / count(nonzero img where slic-1==s)

#define BATCH 8
#define HW (512 * 512)
#define CH 32
#define NSEG 256
#define DROW NSEG
#define ROWS (NSEG + 1)

#define WPB 2
#define BPB 55                              // 440 blocks = one wave @3/SM
#define GRID_ACC (BATCH * BPB)
#define CHUNK ((HW + BPB - 1) / BPB)        // 4767

#define ACCF (ROWS * CH)                    // 8224 floats per warp accumulator
#define SMEM_BYTES (WPB * ACCF * 4)         // 65792 -> 3 blocks/SM

#define PREP_BLOCKS 1024
#define PIX_PER_PREP (BATCH * HW / PREP_BLOCKS)   // 2048
#define CNT_BLK_PER_BATCH (PREP_BLOCKS / BATCH)   // 128

__device__ float g_part[GRID_ACC][NSEG * CH];     // per-block sum partials
__device__ float g_cntp[PREP_BLOCKS][NSEG];       // per-prep-block pixel counts
__device__ float g_zc[BATCH][NSEG][CH];           // exact-zero corrections.
// INVARIANT: g_zc == 0 at every kernel_launch entry (finalize re-zeros).

// ---------------------------------------------------------------------------
// Kernel 1: per-segment pixel counts from slic (int4 x2 per thread).
// ---------------------------------------------------------------------------
__global__ void prep_kernel(const int* __restrict__ slic) {
    __shared__ int cnt[NSEG];
    const int t = threadIdx.x;
    cnt[t] = 0;
    __syncthreads();

    const int4* p = (const int4*)(slic + blockIdx.x * PIX_PER_PREP);
    int4 a = p[t];
    int4 b = p[256 + t];
    if (a.x) atomicAdd(&cnt[a.x - 1], 1);
    if (a.y) atomicAdd(&cnt[a.y - 1], 1);
    if (a.z) atomicAdd(&cnt[a.z - 1], 1);
    if (a.w) atomicAdd(&cnt[a.w - 1], 1);
    if (b.x) atomicAdd(&cnt[b.x - 1], 1);
    if (b.y) atomicAdd(&cnt[b.y - 1], 1);
    if (b.z) atomicAdd(&cnt[b.z - 1], 1);
    if (b.w) atomicAdd(&cnt[b.w - 1], 1);
    __syncthreads();
    g_cntp[blockIdx.x][t] = (float)cnt[t];
}

// ---------------------------------------------------------------------------
// Phase-2: 16-pixel unconditional depth-2-repair RMW (R3-proven, branch-free).
// ---------------------------------------------------------------------------
__device__ __forceinline__ void process16(
    const float v[16], int mysv, float* __restrict__ acc, int batch, int lane)
{
    const unsigned FULL = 0xffffffffu;
    int myrow = (mysv == 0) ? DROW : (mysv - 1);
    int row[16];
    #pragma unroll
    for (int u = 0; u < 16; ++u) row[u] = __shfl_sync(FULL, myrow, u);

    float p0 = acc[row[0] * CH + lane];
    float p1 = acc[row[1] * CH + lane];
    int   lr = -1, l2r = -1;
    float lv = 0.f, l2v = 0.f;
    bool  zany = false;
    #pragma unroll
    for (int u = 0; u < 16; ++u) {
        float a = p0;
        a = (row[u] == l2r) ? l2v : a;          // repair vs store at u-2
        a = (row[u] == lr)  ? lv  : a;          // repair vs store at u-1
        zany |= (v[u] == 0.0f);
        a += v[u];
        float np = 0.0f;
        if (u + 2 < 16) np = acc[row[u + 2] * CH + lane];  // prefetch first
        acc[row[u] * CH + lane] = a;
        l2r = lr;  l2v = lv;
        lr = row[u]; lv = a;
        p0 = p1; p1 = np;
    }

    // Rare: exact-zero entries (warp-uniformly not taken for Gaussian data).
    if (__ballot_sync(FULL, zany)) {
        #pragma unroll
        for (int u = 0; u < 16; ++u)
            if (v[u] == 0.0f && row[u] != DROW)
                atomicAdd(&g_zc[batch][row[u]][lane], 1.0f);
    }
}

// ---------------------------------------------------------------------------
// Kernel 2: segmented accumulation, depth-3 software pipeline (prefetch r+2).
// Warp w handles pixels [start + r*32 + w*16, +16) each round.
// ---------------------------------------------------------------------------
__global__ void __launch_bounds__(WPB * 32, 3)
accum_kernel(const float* __restrict__ img, const int* __restrict__ slic) {
    extern __shared__ float smem[];
    const int warp = threadIdx.x >> 5;
    const int lane = threadIdx.x & 31;
    float* acc = smem + warp * ACCF;

    float4* a4 = (float4*)acc;
    for (int i = lane; i < ACCF / 4; i += 32)
        a4[i] = make_float4(0.f, 0.f, 0.f, 0.f);
    __syncwarp();

    const int batch = blockIdx.x / BPB;
    const int blk   = blockIdx.x % BPB;
    const float* imgb  = img  + (size_t)batch * HW * CH;
    const int*   slicb = slic + (size_t)batch * HW;

    const int start = blk * CHUNK;
    int end = start + CHUNK; if (end > HW) end = HW;
    const int n = end - start;
    const int nfull = n >> 5;                   // 32-px block rounds

    const float* ib = imgb + (size_t)(start + warp * 16) * CH + lane;
    const int*   sp = slicb + start + warp * 16;

    float v0[16], v1[16];
    int s0 = 0, s1 = 0;
    if (nfull > 0) {
        #pragma unroll
        for (int u = 0; u < 16; ++u) v0[u] = __ldcs(ib + u * CH);
        s0 = sp[lane & 15];
    }
    if (nfull > 1) {
        #pragma unroll
        for (int u = 0; u < 16; ++u) v1[u] = __ldcs(ib + (32 + u) * CH);
        s1 = sp[32 + (lane & 15)];
    }

    for (int r = 0; r < nfull; ++r) {
        float vn[16];
        int sn = 0;
        if (r + 2 < nfull) {                    // warp-uniform, prefetch r+2
            #pragma unroll
            for (int u = 0; u < 16; ++u) vn[u] = __ldcs(ib + (64 + u) * CH);
            sn = sp[64 + (lane & 15)];
        } else {
            #pragma unroll
            for (int u = 0; u < 16; ++u) vn[u] = 0.0f;
        }

        process16(v0, s0, acc, batch, lane);

        #pragma unroll
        for (int u = 0; u < 16; ++u) { v0[u] = v1[u]; v1[u] = vn[u]; }
        s0 = s1; s1 = sn;
        ib += 32 * CH; sp += 32;
    }

    // Tail: < 32 pixels.
    for (int p = start + (nfull << 5) + warp; p < end; p += WPB) {
        int s = slicb[p];
        int rw = (s == 0) ? DROW : (s - 1);
        float x = imgb[(size_t)p * CH + lane];
        acc[rw * CH + lane] += x;
        if (x == 0.0f && rw != DROW)
            atomicAdd(&g_zc[batch][rw][lane], 1.0f);
    }

    // Merge warps; stream 256 real sum rows to global.
    __syncthreads();
    const float4* p0w = (const float4*)(smem);
    const float4* p1w = (const float4*)(smem + ACCF);
    float4* outp = (float4*)g_part[blockIdx.x];
    #pragma unroll 4
    for (int i = threadIdx.x; i < NSEG * CH / 4; i += WPB * 32) {
        float4 a = p0w[i], b = p1w[i];
        a.x += b.x; a.y += b.y; a.z += b.z; a.w += b.w;
        outp[i] = a;
    }
}

// ---------------------------------------------------------------------------
// Kernel 3: 4-way k-split reduction + divide. grid 1024 x 256.
// ---------------------------------------------------------------------------
__global__ void finalize_kernel(float* __restrict__ out) {
    __shared__ float ssum[256], scnt[256];
    const int t = threadIdx.x;
    const int slice = t >> 6;                          // 0..3
    const int o = (blockIdx.x << 6) | (t & 63);        // output id 0..65535
    const int c = o & (CH - 1);
    const int s = (o >> 5) & (NSEG - 1);
    const int b = o >> 13;

    // Sum partials: 55 per batch, split 14/14/14/13.
    float sum = 0.0f;
    {
        int k0 = slice * 14, k1 = k0 + 14; if (k1 > BPB) k1 = BPB;
        int pb = b * BPB;
        for (int k = k0; k < k1; ++k)
            sum += g_part[pb + k][s * CH + c];         // coalesced over c
    }
    // Counts: 128 per batch, split 32 each.
    float cn = 0.0f;
    {
        int k0 = slice * 32, k1 = k0 + 32;
        int cb = b * CNT_BLK_PER_BATCH;
        #pragma unroll 8
        for (int k = k0; k < k1; ++k)
            cn += g_cntp[cb + k][s];                   // warp-broadcast
    }
    ssum[t] = sum; scnt[t] = cn;
    __syncthreads();

    if (t < 64) {
        sum = ssum[t] + ssum[t + 64] + ssum[t + 128] + ssum[t + 192];
        cn  = scnt[t] + scnt[t + 64] + scnt[t + 128] + scnt[t + 192];
        cn -= g_zc[b][s][c];
        g_zc[b][s][c] = 0.0f;                          // restore invariant
        out[((size_t)s * BATCH + b) * CH + c] = sum / cn;
    }
}

// ---------------------------------------------------------------------------
extern "C" void kernel_launch(void* const* d_in, const int* in_sizes, int n_in,
                              void* d_out, int out_size) {
    const float* img  = (const float*)d_in[0];
    const int*   slic = (const int*)d_in[1];
    float* out = (float*)d_out;

    prep_kernel<<<PREP_BLOCKS, 256>>>(slic);

    cudaFuncSetAttribute(accum_kernel,
                         cudaFuncAttributeMaxDynamicSharedMemorySize, SMEM_BYTES);
    accum_kernel<<<GRID_ACC, WPB * 32, SMEM_BYTES>>>(img, slic);

    finalize_kernel<<<1024, 256>>>(out);
}

// round 6
// speedup vs baseline: 1.8887x; 1.2549x over previous
#include <cuda_runtime.h>
#include <cuda_bf16.h>
#include <cstdint>

// image_output: [8, 512, 512, 32] f32; slic: [8,512,512,1] i32 in [0,256]
// out[s][b][c] = sum(img where slic-1==s) / count(nonzero img where slic-1==s)

#define BATCH 8
#define HW (512 * 512)
#define CH 32
#define NSEG 256
#define DROW NSEG
#define ROWS (NSEG + 1)

#define WPB 2
#define BPB 55                              // 440 blocks = one wave @3/SM
#define GRID_ACC (BATCH * BPB)
#define CHUNK ((HW + BPB - 1) / BPB)        // 4767

#define ACCF (ROWS * CH)                    // 8224 floats per warp accumulator
#define SMEM_BYTES (WPB * ACCF * 4)         // 65792 -> 3 blocks/SM

#define PREP_BLOCKS 1024
#define PIX_PER_PREP (BATCH * HW / PREP_BLOCKS)   // 2048
#define CNT_BLK_PER_BATCH (PREP_BLOCKS / BATCH)   // 128

__device__ float g_part[GRID_ACC][NSEG * CH];     // per-block sum partials
__device__ float g_cntp[PREP_BLOCKS][NSEG];       // per-prep-block pixel counts
__device__ float g_zc[BATCH][NSEG][CH];           // exact-zero corrections.
// INVARIANT: g_zc == 0 at every kernel_launch entry (finalize re-zeros).

// ---------------------------------------------------------------------------
// Kernel 1: per-segment pixel counts from slic (int4 x2 per thread).
// ---------------------------------------------------------------------------
__global__ void prep_kernel(const int* __restrict__ slic) {
    __shared__ int cnt[NSEG];
    const int t = threadIdx.x;
    cnt[t] = 0;
    __syncthreads();

    const int4* p = (const int4*)(slic + blockIdx.x * PIX_PER_PREP);
    int4 a = p[t];
    int4 b = p[256 + t];
    if (a.x) atomicAdd(&cnt[a.x - 1], 1);
    if (a.y) atomicAdd(&cnt[a.y - 1], 1);
    if (a.z) atomicAdd(&cnt[a.z - 1], 1);
    if (a.w) atomicAdd(&cnt[a.w - 1], 1);
    if (b.x) atomicAdd(&cnt[b.x - 1], 1);
    if (b.y) atomicAdd(&cnt[b.y - 1], 1);
    if (b.z) atomicAdd(&cnt[b.z - 1], 1);
    if (b.w) atomicAdd(&cnt[b.w - 1], 1);
    __syncthreads();
    g_cntp[blockIdx.x][t] = (float)cnt[t];
}

// ---------------------------------------------------------------------------
// 16-pixel unconditional depth-2-repair smem RMW (exact, branch-free).
// zacc accumulates "saw an exact-zero value" per lane (handled after loop).
// ---------------------------------------------------------------------------
__device__ __forceinline__ void process16(
    const float v[16], int mysv, float* __restrict__ acc, int lane, bool& zacc)
{
    const unsigned FULL = 0xffffffffu;
    int myrow = (mysv == 0) ? DROW : (mysv - 1);
    int row[16];
    #pragma unroll
    for (int u = 0; u < 16; ++u) row[u] = __shfl_sync(FULL, myrow, u);

    float p0 = acc[row[0] * CH + lane];
    float p1 = acc[row[1] * CH + lane];
    int   lr = -1, l2r = -1;
    float lv = 0.f, l2v = 0.f;
    #pragma unroll
    for (int u = 0; u < 16; ++u) {
        float a = p0;
        a = (row[u] == l2r) ? l2v : a;          // repair vs store at u-2
        a = (row[u] == lr)  ? lv  : a;          // repair vs store at u-1
        zacc |= (v[u] == 0.0f);
        a += v[u];
        float np = 0.0f;
        if (u + 2 < 16) np = acc[row[u + 2] * CH + lane];  // prefetch first
        acc[row[u] * CH + lane] = a;
        l2r = lr;  l2v = lv;
        lr = row[u]; lv = a;
        p0 = p1; p1 = np;
    }
}

// ---------------------------------------------------------------------------
// Kernel 2: segmented accumulation. Depth-4 unrolled register ring (prefetch
// distance 3, no copy-MOVs), clamped branchless prefetch, warp-private acc.
// ---------------------------------------------------------------------------
#define LOAD_ROUND(BUF, SV, k) do {                                          \
    int pb_ = start + (int)(k) * 32 + warp * 16;                             \
    pb_ = (pb_ > end - 16) ? (end - 16) : pb_;   /* clamp: always in range */\
    const float* ibp_ = imgb + (size_t)pb_ * CH + lane;                      \
    _Pragma("unroll")                                                        \
    for (int u_ = 0; u_ < 16; ++u_) BUF[u_] = __ldcs(ibp_ + u_ * CH);        \
    SV = slicb[pb_ + (lane & 15)];                                           \
} while (0)

__global__ void __launch_bounds__(WPB * 32, 3)
accum_kernel(const float* __restrict__ img, const int* __restrict__ slic) {
    extern __shared__ float smem[];
    __shared__ int zflag[WPB];
    const int warp = threadIdx.x >> 5;
    const int lane = threadIdx.x & 31;
    float* acc = smem + warp * ACCF;
    if (lane == 0) zflag[warp] = 0;

    float4* a4 = (float4*)acc;
    for (int i = lane; i < ACCF / 4; i += 32)
        a4[i] = make_float4(0.f, 0.f, 0.f, 0.f);
    __syncwarp();

    const int batch = blockIdx.x / BPB;
    const int blk   = blockIdx.x % BPB;
    const float* imgb  = img  + (size_t)batch * HW * CH;
    const int*   slicb = slic + (size_t)batch * HW;

    const int start = blk * CHUNK;
    int end = start + CHUNK; if (end > HW) end = HW;
    const int n = end - start;
    const int nfull = n >> 5;                   // 32-px block rounds (>=147)

    const unsigned FULL = 0xffffffffu;
    bool zacc = false;

    float B0[16], B1[16], B2[16], B3[16];
    int   S0, S1, S2, S3;
    LOAD_ROUND(B0, S0, 0);
    LOAD_ROUND(B1, S1, 1);
    LOAD_ROUND(B2, S2, 2);

    int r = 0;
    for (; r + 4 <= nfull; r += 4) {
        LOAD_ROUND(B3, S3, r + 3); process16(B0, S0, acc, lane, zacc);
        LOAD_ROUND(B0, S0, r + 4); process16(B1, S1, acc, lane, zacc);
        LOAD_ROUND(B1, S1, r + 5); process16(B2, S2, acc, lane, zacc);
        LOAD_ROUND(B2, S2, r + 6); process16(B3, S3, acc, lane, zacc);
    }
    const int rem = nfull - r;
    if (rem > 0) process16(B0, S0, acc, lane, zacc);
    if (rem > 1) process16(B1, S1, acc, lane, zacc);
    if (rem > 2) process16(B2, S2, acc, lane, zacc);

    // Tail: < 32 pixels.
    for (int p = start + (nfull << 5) + warp; p < end; p += WPB) {
        int s = slicb[p];
        int rw = (s == 0) ? DROW : (s - 1);
        float x = imgb[(size_t)p * CH + lane];
        acc[rw * CH + lane] += x;
        zacc |= (x == 0.0f);
    }

    if (__ballot_sync(FULL, zacc) && lane == 0) zflag[warp] = 1;

    // Merge warps; stream 256 real sum rows to global.
    __syncthreads();
    const float4* p0w = (const float4*)(smem);
    const float4* p1w = (const float4*)(smem + ACCF);
    float4* outp = (float4*)g_part[blockIdx.x];
    #pragma unroll 4
    for (int i = threadIdx.x; i < NSEG * CH / 4; i += WPB * 32) {
        float4 a = p0w[i], b = p1w[i];
        a.x += b.x; a.y += b.y; a.z += b.z; a.w += b.w;
        outp[i] = a;
    }

    // Exact-zero correction path (essentially never taken; exact when it is).
    if (zflag[0] | zflag[1]) {
        for (int p = start + warp; p < end; p += WPB) {
            int s = slicb[p];
            if (s == 0) continue;
            float x = imgb[(size_t)p * CH + lane];
            if (x == 0.0f) atomicAdd(&g_zc[batch][s - 1][lane], 1.0f);
        }
    }
}

// ---------------------------------------------------------------------------
// Kernel 3: 4-way k-split reduction + divide. grid 1024 x 256.
// ---------------------------------------------------------------------------
__global__ void finalize_kernel(float* __restrict__ out) {
    __shared__ float ssum[256], scnt[256];
    const int t = threadIdx.x;
    const int slice = t >> 6;                          // 0..3
    const int o = (blockIdx.x << 6) | (t & 63);        // output id 0..65535
    const int c = o & (CH - 1);
    const int s = (o >> 5) & (NSEG - 1);
    const int b = o >> 13;

    float sum = 0.0f;
    {
        int k0 = slice * 14, k1 = k0 + 14; if (k1 > BPB) k1 = BPB;
        int pb = b * BPB;
        for (int k = k0; k < k1; ++k)
            sum += g_part[pb + k][s * CH + c];         // coalesced over c
    }
    float cn = 0.0f;
    {
        int k0 = slice * 32, k1 = k0 + 32;
        int cb = b * CNT_BLK_PER_BATCH;
        #pragma unroll 8
        for (int k = k0; k < k1; ++k)
            cn += g_cntp[cb + k][s];                   // warp-broadcast
    }
    ssum[t] = sum; scnt[t] = cn;
    __syncthreads();

    if (t < 64) {
        sum = ssum[t] + ssum[t + 64] + ssum[t + 128] + ssum[t + 192];
        cn  = scnt[t] + scnt[t + 64] + scnt[t + 128] + scnt[t + 192];
        cn -= g_zc[b][s][c];
        g_zc[b][s][c] = 0.0f;                          // restore invariant
        out[((size_t)s * BATCH + b) * CH + c] = sum / cn;
    }
}

// ---------------------------------------------------------------------------
extern "C" void kernel_launch(void* const* d_in, const int* in_sizes, int n_in,
                              void* d_out, int out_size) {
    const float* img  = (const float*)d_in[0];
    const int*   slic = (const int*)d_in[1];
    float* out = (float*)d_out;

    prep_kernel<<<PREP_BLOCKS, 256>>>(slic);

    cudaFuncSetAttribute(accum_kernel,
                         cudaFuncAttributeMaxDynamicSharedMemorySize, SMEM_BYTES);
    accum_kernel<<<GRID_ACC, WPB * 32, SMEM_BYTES>>>(img, slic);

    finalize_kernel<<<1024, 256>>>(out);
}